// round 15
// baseline (speedup 1.0000x reference)
#include <cuda_runtime.h>
#include <cuda_fp16.h>

#define NTOK 16384
#define NEXP 64
#define DIM  2048
#define KCH  64
#define NCHUNK (DIM / KCH)      // 32
#define TOKB 128
#define THREADS 512
#define ROWH 72                 // 144B rows (72 halfs)
#define XSPLITB (TOKB * 144)    // 18432 B per X split tile
#define XBUFB   (2 * XSPLITB)   // 36864 B per X buffer
#define WSPLITB (64 * 144)      // 9216 B per W split tile
#define WBUFB   (2 * WSPLITB)   // 18432 B per W buffer
#define NBUF 3
// dynamic smem: X 3 bufs, W 3 bufs, bias
#define XOFF 0
#define WOFF (NBUF * XBUFB)         // 110592
#define BOFF (WOFF + NBUF * WBUFB)  // 165888
#define SMTOT (BOFF + 256)          // 166144
#define INV256 0.00390625f

typedef unsigned long long ull;

// W pre-scaled x256, fp16 2-split, padded: gW[c][split][exp][ROWH]  (18432B per chunk)
__device__ __align__(16) __half gW[NCHUNK * 2 * NEXP * ROWH];

// ---------- helpers ----------
__device__ __forceinline__ unsigned smem_u32(const void* p) {
    unsigned a;
    asm("{ .reg .u64 t; cvta.to.shared.u64 t, %1; cvt.u32.u64 %0, t; }" : "=r"(a) : "l"(p));
    return a;
}
__device__ __forceinline__ void cpasync16(unsigned s, const void* g) {
    asm volatile("cp.async.cg.shared.global [%0], [%1], 16;" :: "r"(s), "l"(g));
}
__device__ __forceinline__ void ldm4(unsigned* r, unsigned addr) {
    asm volatile("ldmatrix.sync.aligned.m8n8.x4.shared.b16 {%0,%1,%2,%3}, [%4];"
                 : "=r"(r[0]), "=r"(r[1]), "=r"(r[2]), "=r"(r[3]) : "r"(addr));
}
__device__ __forceinline__ void mma16816(float* d, const unsigned* a, const unsigned* b) {
    asm volatile("mma.sync.aligned.m16n8k16.row.col.f32.f16.f16.f32 "
                 "{%0,%1,%2,%3}, {%4,%5,%6,%7}, {%8,%9}, {%0,%1,%2,%3};"
                 : "+f"(d[0]), "+f"(d[1]), "+f"(d[2]), "+f"(d[3])
                 : "r"(a[0]), "r"(a[1]), "r"(a[2]), "r"(a[3]), "r"(b[0]), "r"(b[1]));
}
__device__ __forceinline__ void bar_arrive(int id) {
    asm volatile("bar.arrive %0, %1;" :: "r"(id), "r"(THREADS));
}
__device__ __forceinline__ void bar_wait(int id) {
    asm volatile("bar.sync %0, %1;" :: "r"(id), "r"(THREADS));
}

// ---------- kernel 1: scale + split + pad W (proven layout) ----------
__global__ void prep_W(const float* __restrict__ W) {
    int i = blockIdx.x * blockDim.x + threadIdx.x;
    if (i >= NEXP * DIM) return;
    int e = i >> 11, k = i & (DIM - 1);
    int c = k >> 6, kin = k & 63;
    float x = W[i] * 256.0f;
    __half h = __float2half_rn(x);
    float r = x - __half2float(h);
    __half m = __float2half_rn(r);
    gW[((c * 2 + 0) * NEXP + e) * ROWH + kin] = h;
    gW[((c * 2 + 1) * NEXP + e) * ROWH + kin] = m;
}

// ---------- kernel 2: warp-specialized HMMA GEMM, named-barrier handoff ----------
__global__ __launch_bounds__(THREADS, 1)
void gate_hmma(const float* __restrict__ inp,
               const float* __restrict__ bias,
               float* __restrict__ out,
               int out_size) {
    extern __shared__ __align__(16) char smem[];
    const unsigned SB = smem_u32(smem);
    const unsigned XD = SB + XOFF;
    const unsigned WD = SB + WOFF;
    float* bsm = (float*)(smem + BOFF);

    const int tid  = threadIdx.x;
    const int wid  = tid >> 5;
    const int lane = tid & 31;
    const int tokBase = blockIdx.x * TOKB;

    const bool consumer = (wid < 8);
    const int tg = wid & 3;          // consumer token group (32 tokens each)
    const int kh = (wid >> 2) & 1;   // consumer K half

    if (tid < 64) bsm[tid] = bias[tid];

    const unsigned aBase = (unsigned)((tg * 32 + (lane & 15)) * 144 + kh * 64 + ((lane >> 4) << 4));
    const unsigned bBase = (unsigned)(((lane & 7) + ((lane >> 4) << 3)) * 144 + kh * 64 + (((lane >> 3) & 1) << 4));

    float d0[8][4], d1[8][4];
#pragma unroll
    for (int j = 0; j < 8; j++)
#pragma unroll
        for (int q = 0; q < 4; q++) { d0[j][q] = 0.f; d1[j][q] = 0.f; }

    if (consumer) {
        // ================= CONSUMER LOOP =================
        for (int c = 0; c < NCHUNK; c++) {
            const int b = c % NBUF;
            bar_wait(1 + b);                 // FULL(b): producer data landed
            const unsigned xA = XD + b * XBUFB + aBase;
            const unsigned wA = WD + b * WBUFB + bBase;
#pragma unroll
            for (int ks = 0; ks < 2; ks++) {
                const unsigned xk = xA + ks * 32;
                const unsigned wk = wA + ks * 32;
                unsigned ah0[4], ah1[4], am0[4], am1[4];
                unsigned bb[4][4];
                ldm4(ah0, xk);
                ldm4(ah1, xk + 2304);
#pragma unroll
                for (int g = 0; g < 4; g++) ldm4(bb[g], wk + g * 2304);
                // wave 1: hh
#pragma unroll
                for (int g = 0; g < 4; g++) {
                    mma16816(d0[2*g],   ah0, bb[g]);  mma16816(d0[2*g+1], ah0, bb[g] + 2);
                    mma16816(d1[2*g],   ah1, bb[g]);  mma16816(d1[2*g+1], ah1, bb[g] + 2);
                }
                ldm4(am0, xk + XSPLITB);
                ldm4(am1, xk + XSPLITB + 2304);
                // wave 2: mh
#pragma unroll
                for (int g = 0; g < 4; g++) {
                    mma16816(d0[2*g],   am0, bb[g]);  mma16816(d0[2*g+1], am0, bb[g] + 2);
                    mma16816(d1[2*g],   am1, bb[g]);  mma16816(d1[2*g+1], am1, bb[g] + 2);
                }
#pragma unroll
                for (int g = 0; g < 4; g++) ldm4(bb[g], wk + WSPLITB + g * 2304);
                // wave 3: hm
#pragma unroll
                for (int g = 0; g < 4; g++) {
                    mma16816(d0[2*g],   ah0, bb[g]);  mma16816(d0[2*g+1], ah0, bb[g] + 2);
                    mma16816(d1[2*g],   ah1, bb[g]);  mma16816(d1[2*g+1], ah1, bb[g] + 2);
                }
            }
            bar_arrive(4 + b);               // EMPTY(b): buffer free for reuse
        }
    } else {
        // ================= PRODUCER LOOP =================
        const int pw = wid - 8;
        const float* pSrc = inp + (size_t)(tokBase + pw * 16 + (lane >> 4)) * DIM + (lane & 15) * 4;

        float4 xr0[8], xr1[8];
        auto ldgX = [&](int n, float4* v) {
#pragma unroll
            for (int i = 0; i < 8; i++)
                v[i] = *(const float4*)(pSrc + (size_t)n * KCH + 2 * i * DIM);
        };
        auto cpW = [&](int n, int nb) {
            int p = tid - 256;
#pragma unroll
            for (int j = 0; j < 5; j++) {
                int o = p + j * 256;
                if (o < WBUFB / 16)
                    cpasync16(WD + nb * WBUFB + o * 16,
                              (const char*)gW + (size_t)n * WBUFB + o * 16);
            }
            asm volatile("cp.async.commit_group;");
        };
        auto stsX = [&](const float4* v, int nb) {
#pragma unroll
            for (int i = 0; i < 8; i++) {
                __half2 h2a = __floats2half2_rn(v[i].x, v[i].y);
                __half2 h2b = __floats2half2_rn(v[i].z, v[i].w);
                float2 fa = __half22float2(h2a);
                float2 fb = __half22float2(h2b);
                __half2 m2a = __floats2half2_rn(v[i].x - fa.x, v[i].y - fa.y);
                __half2 m2b = __floats2half2_rn(v[i].z - fb.x, v[i].w - fb.y);
                ull hull = (ull)(*(unsigned*)&h2a) | ((ull)(*(unsigned*)&h2b) << 32);
                ull mull = (ull)(*(unsigned*)&m2a) | ((ull)(*(unsigned*)&m2b) << 32);
                int t = pw * 16 + 2 * i + (lane >> 4);
                char* xh = smem + XOFF + nb * XBUFB + t * 144 + (lane & 15) * 8;
                *(ull*)xh = hull;
                *(ull*)(xh + XSPLITB) = mull;
            }
        };

        ldgX(0, xr0);
        for (int c = 0; c < NCHUNK; c++) {
            const int b = c % NBUF;
            const float4* cur = (c & 1) ? xr1 : xr0;
            float4* nxt = (c & 1) ? xr0 : xr1;
            if (c + 1 < NCHUNK) ldgX(c + 1, nxt);   // issue a full iteration early
            if (c >= NBUF) bar_wait(4 + b);          // EMPTY(b): consumers released it
            cpW(c, b);
            stsX(cur, b);
            asm volatile("cp.async.wait_group 0;");
            bar_arrive(1 + b);                       // FULL(b): data ready
        }
    }
    __syncthreads();   // converge all warps before scratch reuse

    // ---- reduce across the 2 K-halves (scratch reuses X staging smem) ----
    float* scr = (float*)smem;   // rows of 68 floats (272B)

    if (consumer && kh == 1) {
        int row = tg * 32 + lane;
#pragma unroll
        for (int j = 0; j < 8; j++)
            *(float4*)(scr + row * 68 + j * 4) = make_float4(d0[j][0], d0[j][1], d0[j][2], d0[j][3]);
#pragma unroll
        for (int j = 0; j < 8; j++)
            *(float4*)(scr + row * 68 + 32 + j * 4) = make_float4(d1[j][0], d1[j][1], d1[j][2], d1[j][3]);
    }
    __syncthreads();

    if (consumer && kh == 0) {
        int row = tg * 32 + lane;
#pragma unroll
        for (int j = 0; j < 8; j++) {
            float4 v = *(const float4*)(scr + row * 68 + j * 4);
            d0[j][0] += v.x; d0[j][1] += v.y; d0[j][2] += v.z; d0[j][3] += v.w;
        }
#pragma unroll
        for (int j = 0; j < 8; j++) {
            float4 v = *(const float4*)(scr + row * 68 + 32 + j * 4);
            d1[j][0] += v.x; d1[j][1] += v.y; d1[j][2] += v.z; d1[j][3] += v.w;
        }

        // ---- epilogue: unscale, +bias, top-2 over 64, softmax ----
        const int half = out_size >> 1;
#pragma unroll
        for (int mt = 0; mt < 2; mt++) {
#pragma unroll
            for (int rh = 0; rh < 2; rh++) {
                float v0 = -3.4e38f, v1 = -3.4e38f;
                int   i0 = -1,       i1 = -1;
#pragma unroll
                for (int j = 0; j < 8; j++) {
#pragma unroll
                    for (int v = 0; v < 2; v++) {
                        int e = j * 8 + (lane & 3) * 2 + v;
                        float dv = (mt == 0) ? d0[j][rh * 2 + v] : d1[j][rh * 2 + v];
                        float f = dv * INV256 + bsm[e];
                        if (f > v0)      { v1 = v0; i1 = i0; v0 = f; i0 = e; }
                        else if (f > v1) { v1 = f;  i1 = e; }
                    }
                }
#pragma unroll
                for (int ofs = 1; ofs < 4; ofs <<= 1) {
                    float u0 = __shfl_xor_sync(0xFFFFFFFFu, v0, ofs);
                    float u1 = __shfl_xor_sync(0xFFFFFFFFu, v1, ofs);
                    int   j0 = __shfl_xor_sync(0xFFFFFFFFu, i0, ofs);
                    int   j1 = __shfl_xor_sync(0xFFFFFFFFu, i1, ofs);
                    bool afirst = (v0 > u0) || (v0 == u0 && i0 < j0);
                    float nv0, nv1; int ni0, ni1;
                    if (afirst) {
                        nv0 = v0; ni0 = i0;
                        bool s = (u0 > v1) || (u0 == v1 && j0 < i1);
                        nv1 = s ? u0 : v1; ni1 = s ? j0 : i1;
                    } else {
                        nv0 = u0; ni0 = j0;
                        bool s = (v0 > u1) || (v0 == u1 && i0 < j1);
                        nv1 = s ? v0 : u1; ni1 = s ? i0 : j1;
                    }
                    v0 = nv0; v1 = nv1; i0 = ni0; i1 = ni1;
                }
                if ((lane & 3) == 0) {
                    int tok = tokBase + tg * 32 + mt * 16 + rh * 8 + (lane >> 2);
                    float ex = expf(v1 - v0);
                    float s0 = 1.0f / (1.0f + ex);
                    float s1 = ex * s0;
                    out[tok * 2 + 0] = (float)i0;
                    out[tok * 2 + 1] = (float)i1;
                    out[half + tok * 2 + 0] = s0;
                    out[half + tok * 2 + 1] = s1;
                }
            }
        }
    }
}

extern "C" void kernel_launch(void* const* d_in, const int* in_sizes, int n_in,
                              void* d_out, int out_size) {
    const float* inp  = (const float*)d_in[0];   // [16384, 2048]
    const float* W    = (const float*)d_in[1];   // [64, 2048]
    const float* bias = (const float*)d_in[2];   // [64]
    float* out = (float*)d_out;

    cudaFuncSetAttribute(gate_hmma, cudaFuncAttributeMaxDynamicSharedMemorySize, SMTOT);
    prep_W<<<(NEXP * DIM + 255) / 256, 256>>>(W);
    gate_hmma<<<NTOK / TOKB, THREADS, SMTOT>>>(inp, bias, out, out_size);
}

// round 16
// speedup vs baseline: 1.0969x; 1.0969x over previous
#include <cuda_runtime.h>
#include <cuda_fp16.h>

#define NTOK 16384
#define NEXP 64
#define DIM  2048
#define KCH  64
#define NCHUNK (DIM / KCH)      // 32
#define NSTAGE (NCHUNK / 2)     // 16 (2 chunks per stage)
#define TOKB 128
#define THREADS 512
#define ROWH 72                 // 144B rows (72 halfs)
#define XSPLITB (TOKB * 144)    // 18432 B per X split tile
#define XBUFB   (2 * XSPLITB)   // 36864 B per X chunk-tile (2 splits)
#define WSPLITB (64 * 144)      // 9216 B per W split tile
#define WBUFB   (2 * WSPLITB)   // 18432 B per W chunk-tile
#define XSTAGEB (2 * XBUFB)     // 73728 B per X stage (2 chunks)
#define WSTAGEB (2 * WBUFB)     // 36864 B per W stage
// dynamic smem: X 2 stages, W 2 stages, bias
#define XOFF 0
#define WOFF (2 * XSTAGEB)          // 147456
#define BOFF (WOFF + 2 * WSTAGEB)   // 221184
#define SMTOT (BOFF + 256)          // 221440 (< 227KB cap)
#define INV256 0.00390625f

typedef unsigned long long ull;

// W pre-scaled x256, fp16 2-split, padded: gW[c][split][exp][ROWH]  (18432B per chunk)
__device__ __align__(16) __half gW[NCHUNK * 2 * NEXP * ROWH];

// ---------- helpers ----------
__device__ __forceinline__ unsigned smem_u32(const void* p) {
    unsigned a;
    asm("{ .reg .u64 t; cvta.to.shared.u64 t, %1; cvt.u32.u64 %0, t; }" : "=r"(a) : "l"(p));
    return a;
}
__device__ __forceinline__ void cpasync16(unsigned s, const void* g) {
    asm volatile("cp.async.cg.shared.global [%0], [%1], 16;" :: "r"(s), "l"(g));
}
__device__ __forceinline__ void ldm4(unsigned* r, unsigned addr) {
    asm volatile("ldmatrix.sync.aligned.m8n8.x4.shared.b16 {%0,%1,%2,%3}, [%4];"
                 : "=r"(r[0]), "=r"(r[1]), "=r"(r[2]), "=r"(r[3]) : "r"(addr));
}
__device__ __forceinline__ void mma16816(float* d, const unsigned* a, const unsigned* b) {
    asm volatile("mma.sync.aligned.m16n8k16.row.col.f32.f16.f16.f32 "
                 "{%0,%1,%2,%3}, {%4,%5,%6,%7}, {%8,%9}, {%0,%1,%2,%3};"
                 : "+f"(d[0]), "+f"(d[1]), "+f"(d[2]), "+f"(d[3])
                 : "r"(a[0]), "r"(a[1]), "r"(a[2]), "r"(a[3]), "r"(b[0]), "r"(b[1]));
}

// ---------- kernel 1: scale + split + pad W (proven layout) ----------
__global__ void prep_W(const float* __restrict__ W) {
    int i = blockIdx.x * blockDim.x + threadIdx.x;
    if (i >= NEXP * DIM) return;
    int e = i >> 11, k = i & (DIM - 1);
    int c = k >> 6, kin = k & 63;
    float x = W[i] * 256.0f;
    __half h = __float2half_rn(x);
    float r = x - __half2float(h);
    __half m = __float2half_rn(r);
    gW[((c * 2 + 0) * NEXP + e) * ROWH + kin] = h;
    gW[((c * 2 + 1) * NEXP + e) * ROWH + kin] = m;
}

// ---------- kernel 2: warp-specialized HMMA GEMM, 2-chunk stages ----------
__global__ __launch_bounds__(THREADS, 1)
void gate_hmma(const float* __restrict__ inp,
               const float* __restrict__ bias,
               float* __restrict__ out,
               int out_size) {
    extern __shared__ __align__(16) char smem[];
    const unsigned SB = smem_u32(smem);
    const unsigned XD = SB + XOFF;
    const unsigned WD = SB + WOFF;
    float* bsm = (float*)(smem + BOFF);

    const int tid  = threadIdx.x;
    const int wid  = tid >> 5;
    const int lane = tid & 31;
    const int tokBase = blockIdx.x * TOKB;

    const bool consumer = (wid < 8);
    const int tg = wid & 3;          // consumer token group (32 tokens each)
    const int kh = (wid >> 2) & 1;   // consumer K half

    if (tid < 64) bsm[tid] = bias[tid];

    const unsigned aBase = (unsigned)((tg * 32 + (lane & 15)) * 144 + kh * 64 + ((lane >> 4) << 4));
    const unsigned bBase = (unsigned)(((lane & 7) + ((lane >> 4) << 3)) * 144 + kh * 64 + (((lane >> 3) & 1) << 4));

    float d0[8][4], d1[8][4];
#pragma unroll
    for (int j = 0; j < 8; j++)
#pragma unroll
        for (int q = 0; q < 4; q++) { d0[j][q] = 0.f; d1[j][q] = 0.f; }

    if (consumer) {
        // ================= CONSUMER LOOP =================
        __syncthreads();                      // stage 0 ready
        for (int s = 0; s < NSTAGE; s++) {
            const int b = s & 1;
#pragma unroll
            for (int sub = 0; sub < 2; sub++) {
                const unsigned xA = XD + b * XSTAGEB + sub * XBUFB + aBase;
                const unsigned wA = WD + b * WSTAGEB + sub * WBUFB + bBase;
#pragma unroll
                for (int ks = 0; ks < 2; ks++) {
                    const unsigned xk = xA + ks * 32;
                    const unsigned wk = wA + ks * 32;
                    unsigned ah0[4], ah1[4], am0[4], am1[4];
                    unsigned bb[4][4];
                    ldm4(ah0, xk);
                    ldm4(ah1, xk + 2304);
#pragma unroll
                    for (int g = 0; g < 4; g++) ldm4(bb[g], wk + g * 2304);
                    // wave 1: hh
#pragma unroll
                    for (int g = 0; g < 4; g++) {
                        mma16816(d0[2*g],   ah0, bb[g]);  mma16816(d0[2*g+1], ah0, bb[g] + 2);
                        mma16816(d1[2*g],   ah1, bb[g]);  mma16816(d1[2*g+1], ah1, bb[g] + 2);
                    }
                    ldm4(am0, xk + XSPLITB);
                    ldm4(am1, xk + XSPLITB + 2304);
                    // wave 2: mh
#pragma unroll
                    for (int g = 0; g < 4; g++) {
                        mma16816(d0[2*g],   am0, bb[g]);  mma16816(d0[2*g+1], am0, bb[g] + 2);
                        mma16816(d1[2*g],   am1, bb[g]);  mma16816(d1[2*g+1], am1, bb[g] + 2);
                    }
#pragma unroll
                    for (int g = 0; g < 4; g++) ldm4(bb[g], wk + WSPLITB + g * 2304);
                    // wave 3: hm
#pragma unroll
                    for (int g = 0; g < 4; g++) {
                        mma16816(d0[2*g],   ah0, bb[g]);  mma16816(d0[2*g+1], ah0, bb[g] + 2);
                        mma16816(d1[2*g],   ah1, bb[g]);  mma16816(d1[2*g+1], ah1, bb[g] + 2);
                    }
                }
            }
            __syncthreads();
        }
    } else {
        // ================= PRODUCER LOOP =================
        const int pw = wid - 8;
        const float* pSrc = inp + (size_t)(tokBase + pw * 16 + (lane >> 4)) * DIM + (lane & 15) * 4;

        float4 xr0[8], xr1[8];
        auto ldgX = [&](int n, float4* v) {
#pragma unroll
            for (int i = 0; i < 8; i++)
                v[i] = *(const float4*)(pSrc + (size_t)n * KCH + 2 * i * DIM);
        };
        auto cpW = [&](int n, unsigned dstBase) {
            int p = tid - 256;
#pragma unroll
            for (int j = 0; j < 5; j++) {
                int o = p + j * 256;
                if (o < WBUFB / 16)
                    cpasync16(dstBase + o * 16,
                              (const char*)gW + (size_t)n * WBUFB + o * 16);
            }
        };
        auto stsX = [&](const float4* v, unsigned dstOff) {
#pragma unroll
            for (int i = 0; i < 8; i++) {
                __half2 h2a = __floats2half2_rn(v[i].x, v[i].y);
                __half2 h2b = __floats2half2_rn(v[i].z, v[i].w);
                float2 fa = __half22float2(h2a);
                float2 fb = __half22float2(h2b);
                __half2 m2a = __floats2half2_rn(v[i].x - fa.x, v[i].y - fa.y);
                __half2 m2b = __floats2half2_rn(v[i].z - fb.x, v[i].w - fb.y);
                ull hull = (ull)(*(unsigned*)&h2a) | ((ull)(*(unsigned*)&h2b) << 32);
                ull mull = (ull)(*(unsigned*)&m2a) | ((ull)(*(unsigned*)&m2b) << 32);
                int t = pw * 16 + 2 * i + (lane >> 4);
                char* xh = smem + dstOff + t * 144 + (lane & 15) * 8;
                *(ull*)xh = hull;
                *(ull*)(xh + XSPLITB) = mull;
            }
        };

        // stage s -> buffers: X at XOFF + (s&1)*XSTAGEB [+ sub*XBUFB], W at WD + (s&1)*WSTAGEB [+ sub*WBUFB]
        auto produce = [&](int s) {
            const int b = s & 1;
            ldgX(2 * s, xr0);                 // issue both LDG batches first (MLP)
            ldgX(2 * s + 1, xr1);
            cpW(2 * s,     WD + b * WSTAGEB);
            cpW(2 * s + 1, WD + b * WSTAGEB + WBUFB);
            asm volatile("cp.async.commit_group;");
            stsX(xr0, (unsigned)(XOFF + b * XSTAGEB));           // waits LDG batch 0 via reg dep
            stsX(xr1, (unsigned)(XOFF + b * XSTAGEB + XBUFB));
            asm volatile("cp.async.wait_group 0;");
        };

        produce(0);
        __syncthreads();                      // stage 0 ready
        for (int s = 0; s < NSTAGE; s++) {
            if (s + 1 < NSTAGE) produce(s + 1);
            __syncthreads();
        }
    }
    __syncthreads();   // converge before scratch reuse

    // ---- reduce across the 2 K-halves (scratch reuses X staging smem) ----
    float* scr = (float*)smem;   // rows of 68 floats (272B)

    if (consumer && kh == 1) {
        int row = tg * 32 + lane;
#pragma unroll
        for (int j = 0; j < 8; j++)
            *(float4*)(scr + row * 68 + j * 4) = make_float4(d0[j][0], d0[j][1], d0[j][2], d0[j][3]);
#pragma unroll
        for (int j = 0; j < 8; j++)
            *(float4*)(scr + row * 68 + 32 + j * 4) = make_float4(d1[j][0], d1[j][1], d1[j][2], d1[j][3]);
    }
    __syncthreads();

    if (consumer && kh == 0) {
        int row = tg * 32 + lane;
#pragma unroll
        for (int j = 0; j < 8; j++) {
            float4 v = *(const float4*)(scr + row * 68 + j * 4);
            d0[j][0] += v.x; d0[j][1] += v.y; d0[j][2] += v.z; d0[j][3] += v.w;
        }
#pragma unroll
        for (int j = 0; j < 8; j++) {
            float4 v = *(const float4*)(scr + row * 68 + 32 + j * 4);
            d1[j][0] += v.x; d1[j][1] += v.y; d1[j][2] += v.z; d1[j][3] += v.w;
        }

        // ---- epilogue: unscale, +bias, top-2 over 64, softmax ----
        const int half = out_size >> 1;
#pragma unroll
        for (int mt = 0; mt < 2; mt++) {
#pragma unroll
            for (int rh = 0; rh < 2; rh++) {
                float v0 = -3.4e38f, v1 = -3.4e38f;
                int   i0 = -1,       i1 = -1;
#pragma unroll
                for (int j = 0; j < 8; j++) {
#pragma unroll
                    for (int v = 0; v < 2; v++) {
                        int e = j * 8 + (lane & 3) * 2 + v;
                        float dv = (mt == 0) ? d0[j][rh * 2 + v] : d1[j][rh * 2 + v];
                        float f = dv * INV256 + bsm[e];
                        if (f > v0)      { v1 = v0; i1 = i0; v0 = f; i0 = e; }
                        else if (f > v1) { v1 = f;  i1 = e; }
                    }
                }
#pragma unroll
                for (int ofs = 1; ofs < 4; ofs <<= 1) {
                    float u0 = __shfl_xor_sync(0xFFFFFFFFu, v0, ofs);
                    float u1 = __shfl_xor_sync(0xFFFFFFFFu, v1, ofs);
                    int   j0 = __shfl_xor_sync(0xFFFFFFFFu, i0, ofs);
                    int   j1 = __shfl_xor_sync(0xFFFFFFFFu, i1, ofs);
                    bool afirst = (v0 > u0) || (v0 == u0 && i0 < j0);
                    float nv0, nv1; int ni0, ni1;
                    if (afirst) {
                        nv0 = v0; ni0 = i0;
                        bool sw = (u0 > v1) || (u0 == v1 && j0 < i1);
                        nv1 = sw ? u0 : v1; ni1 = sw ? j0 : i1;
                    } else {
                        nv0 = u0; ni0 = j0;
                        bool sw = (v0 > u1) || (v0 == u1 && i0 < j1);
                        nv1 = sw ? v0 : u1; ni1 = sw ? i0 : j1;
                    }
                    v0 = nv0; v1 = nv1; i0 = ni0; i1 = ni1;
                }
                if ((lane & 3) == 0) {
                    int tok = tokBase + tg * 32 + mt * 16 + rh * 8 + (lane >> 2);
                    float ex = expf(v1 - v0);
                    float s0 = 1.0f / (1.0f + ex);
                    float s1 = ex * s0;
                    out[tok * 2 + 0] = (float)i0;
                    out[tok * 2 + 1] = (float)i1;
                    out[half + tok * 2 + 0] = s0;
                    out[half + tok * 2 + 1] = s1;
                }
            }
        }
    }
}

extern "C" void kernel_launch(void* const* d_in, const int* in_sizes, int n_in,
                              void* d_out, int out_size) {
    const float* inp  = (const float*)d_in[0];   // [16384, 2048]
    const float* W    = (const float*)d_in[1];   // [64, 2048]
    const float* bias = (const float*)d_in[2];   // [64]
    float* out = (float*)d_out;

    cudaFuncSetAttribute(gate_hmma, cudaFuncAttributeMaxDynamicSharedMemorySize, SMTOT);
    prep_W<<<(NEXP * DIM + 255) / 256, 256>>>(W);
    gate_hmma<<<NTOK / TOKB, THREADS, SMTOT>>>(inp, bias, out, out_size);
}